// round 14
// baseline (speedup 1.0000x reference)
#include <cuda_runtime.h>
#include <cuda_bf16.h>
#include <math.h>

#define BD   2
#define SEQ  1024
#define DM   768
#define NH   12
#define HD   64
#define GD   192
// ATT_SCALE * log2(e): scores come out pre-scaled for exp2-based softmax
#define ATT_SCALE2 (0.125f * 1.4426950408889634f)
#define SOFT_C 8.0f

typedef __nv_bfloat16 bf16;

// ------------------------------ scratch ------------------------------------
__device__ __align__(16) bf16 g_qw[BD*NH*SEQ*HD];
__device__ __align__(16) bf16 g_qr[BD*NH*SEQ*HD];
__device__ __align__(16) bf16 g_k [BD*NH*SEQ*HD];
__device__ __align__(16) bf16 g_v [BD*NH*SEQ*HD];
__device__ __align__(16) bf16 g_rh[NH*2048*HD];
__device__ __align__(16) bf16 g_avh[BD*SEQ*DM];
__device__ __align__(16) bf16 g_avl[BD*SEQ*DM];
__device__ __align__(16) bf16 g_woh[DM*DM];
__device__ __align__(16) bf16 g_wol[DM*DM];
__device__ __align__(16) bf16 g_xb [BD*SEQ*DM];
__device__ __align__(16) bf16 g_peb[2047*DM + 64];
__device__ __align__(16) bf16 g_rkb[DM*DM];
__device__ __align__(16) bf16 g_wb [3*4*GD*GD];
__device__ float g_h [BD*SEQ*DM];

// ------------------------------ helpers ------------------------------------
__device__ __forceinline__ unsigned pk(float lo, float hi) {
    __nv_bfloat162 h = __floats2bfloat162_rn(lo, hi);
    return *(unsigned*)&h;
}
__device__ __forceinline__ float ex2(float x) {
    float y;
    asm("ex2.approx.f32 %0, %1;" : "=f"(y) : "f"(x));
    return y;
}
__device__ __forceinline__ unsigned s2u(const void* p) {
    return (unsigned)__cvta_generic_to_shared(p);
}
__device__ __forceinline__ void ldm_x4(unsigned& r0, unsigned& r1, unsigned& r2, unsigned& r3, unsigned a) {
    asm volatile("ldmatrix.sync.aligned.m8n8.x4.shared.b16 {%0,%1,%2,%3},[%4];"
                 : "=r"(r0), "=r"(r1), "=r"(r2), "=r"(r3) : "r"(a));
}
__device__ __forceinline__ void ldm_x4t(unsigned& r0, unsigned& r1, unsigned& r2, unsigned& r3, unsigned a) {
    asm volatile("ldmatrix.sync.aligned.m8n8.x4.trans.shared.b16 {%0,%1,%2,%3},[%4];"
                 : "=r"(r0), "=r"(r1), "=r"(r2), "=r"(r3) : "r"(a));
}
__device__ __forceinline__ void mma_bf16(float* c, const unsigned* a, unsigned b0, unsigned b1) {
    asm volatile("mma.sync.aligned.m16n8k16.row.col.f32.bf16.bf16.f32 "
                 "{%0,%1,%2,%3},{%4,%5,%6,%7},{%8,%9},{%0,%1,%2,%3};"
                 : "+f"(c[0]), "+f"(c[1]), "+f"(c[2]), "+f"(c[3])
                 : "r"(a[0]), "r"(a[1]), "r"(a[2]), "r"(a[3]), "r"(b0), "r"(b1));
}
__device__ __forceinline__ void cpa16(unsigned dst, const void* src, int sz) {
    asm volatile("cp.async.cg.shared.global [%0], [%1], 16, %2;"
                 :: "r"(dst), "l"(src), "r"(sz));
}
#define CP_COMMIT() asm volatile("cp.async.commit_group;")
template<int N> __device__ __forceinline__ void cp_wait() {
    asm volatile("cp.async.wait_group %0;" :: "n"(N));
}

__device__ __forceinline__ void async_bf16_tile(bf16* dst, const bf16* src, int ld,
                                                int maxrow, int tid) {
    #pragma unroll
    for (int it = 0; it < 4; it++) {
        int c = tid + it*128, row = c >> 3, ch = c & 7;
        int sz = (row < maxrow) ? 16 : 0;
        int ar = (row < maxrow) ? row : (maxrow - 1);
        cpa16(s2u((char*)dst + row*128 + ((ch ^ (row&7)) << 4)),
              src + (size_t)ar*ld + ch*8, sz);
    }
}

// B-only MMA loop: c += a @ B(sB), 16 LDSM + 32 MMA
__device__ __forceinline__ void mma_B(float (*c)[4], const unsigned (*a)[4],
                                      const bf16* sB, int lane) {
    #pragma unroll
    for (int nbp = 0; nbp < 4; nbp++) {
        #pragma unroll
        for (int ks = 0; ks < 4; ks++) {
            int vrow = ks*16 + (lane & 15);
            int ch   = nbp*2 + (lane >> 4);
            unsigned b0, b1, b2, b3;
            ldm_x4t(b0, b1, b2, b3,
                    s2u((const char*)sB + vrow*128 + ((ch ^ (vrow&7)) << 4)));
            mma_bf16(c[2*nbp],   a[ks], b0, b1);
            mma_bf16(c[2*nbp+1], a[ks], b2, b3);
        }
    }
}
__device__ __forceinline__ void load_afrag(unsigned (*a)[4], const bf16* sA,
                                           int arow, int csel) {
    #pragma unroll
    for (int ks = 0; ks < 4; ks++) {
        int ch = ks*2 + csel;
        ldm_x4(a[ks][0], a[ks][1], a[ks][2], a[ks][3],
               s2u((const char*)sA + arow*128 + ((ch ^ (arow&7)) << 4)));
    }
}

// ---------------------------------------------------------------------------
// K0: fp32->bf16 conversions + Wo hi/lo split. grid (256, 7)
// ---------------------------------------------------------------------------
__global__ void __launch_bounds__(256) prep_kernel(
    const float* __restrict__ x,  const float* __restrict__ pe,
    const float* __restrict__ rk, const float* __restrict__ Wq,
    const float* __restrict__ Wk, const float* __restrict__ Wv,
    const float* __restrict__ Wo)
{
    const int seg = blockIdx.y;
    if (seg == 6) {
        for (int i = blockIdx.x*256 + threadIdx.x; i < DM*DM/4; i += gridDim.x*256) {
            float4 v = *(const float4*)&Wo[i*4];
            unsigned h0 = pk(v.x, v.y), h1 = pk(v.z, v.w);
            __nv_bfloat162 a = *(__nv_bfloat162*)&h0, b = *(__nv_bfloat162*)&h1;
            unsigned l0 = pk(v.x - __low2float(a), v.y - __high2float(a));
            unsigned l1 = pk(v.z - __low2float(b), v.w - __high2float(b));
            *(uint2*)&g_woh[i*4] = make_uint2(h0, h1);
            *(uint2*)&g_wol[i*4] = make_uint2(l0, l1);
        }
        return;
    }
    const float* src; bf16* dst; int n4;
    switch (seg) {
        case 0: src = x;  dst = g_xb;  n4 = BD*SEQ*DM/4;   break;
        case 1: src = pe; dst = g_peb; n4 = 2047*DM/4;     break;
        case 2: src = rk; dst = g_rkb; n4 = DM*DM/4;       break;
        case 3: src = Wq; dst = g_wb;            n4 = GD*GD; break;
        case 4: src = Wk; dst = g_wb + 4*GD*GD;  n4 = GD*GD; break;
        default: src = Wv; dst = g_wb + 8*GD*GD; n4 = GD*GD; break;
    }
    for (int i = blockIdx.x*256 + threadIdx.x; i < n4; i += gridDim.x*256) {
        float4 v = *(const float4*)&src[i*4];
        *(uint2*)&dst[i*4] = make_uint2(pk(v.x, v.y), pk(v.z, v.w));
    }
}

// ---------------------------------------------------------------------------
// K1a: fused QKV — one CTA computes q/k/v for a (m-tile, head) pair.
// smem: 2 stages x (A, Bq, Bk, Bv) x 8KB = 64KB dynamic.  grid (32, 12)
// ---------------------------------------------------------------------------
#define QKV_SMEM_BYTES 65536

__global__ void __launch_bounds__(128) qkvf_kernel(
    const float* __restrict__ bk, const float* __restrict__ bv,
    const float* __restrict__ rwb, const float* __restrict__ rrb)
{
    extern __shared__ char qsm[];
    #define QT(s, t) ((bf16*)(qsm + (s)*32768 + (t)*8192))
    const int tid = threadIdx.x, lane = tid & 31, w = tid >> 5;
    const int m0 = blockIdx.x * 64;
    const int n  = blockIdx.y;
    const int g  = n / 3, oo0 = (n % 3) * 64;

    const bf16* srcA  = g_xb + (size_t)m0*DM + g*GD;
    const bf16* srcBq = g_wb +              g*GD*GD + oo0;
    const bf16* srcBk = g_wb + 4*GD*GD +    g*GD*GD + oo0;
    const bf16* srcBv = g_wb + 8*GD*GD +    g*GD*GD + oo0;

    float cq[8][4] = {}, ck[8][4] = {}, cv[8][4] = {};

    async_bf16_tile(QT(0,0), srcA,  DM, 64, tid);
    async_bf16_tile(QT(0,1), srcBq, GD, 64, tid);
    async_bf16_tile(QT(0,2), srcBk, GD, 64, tid);
    async_bf16_tile(QT(0,3), srcBv, GD, 64, tid);
    CP_COMMIT();

    const int arow = w*16 + (lane & 15), csel = lane >> 4;
    for (int i = 0; i < 3; i++) {
        int cur = i & 1, nxt = cur ^ 1;
        if (i < 2) {
            int kb = (i+1)*64;
            async_bf16_tile(QT(nxt,0), srcA  + kb, DM, 64, tid);
            async_bf16_tile(QT(nxt,1), srcBq + (size_t)kb*GD, GD, 64, tid);
            async_bf16_tile(QT(nxt,2), srcBk + (size_t)kb*GD, GD, 64, tid);
            async_bf16_tile(QT(nxt,3), srcBv + (size_t)kb*GD, GD, 64, tid);
            CP_COMMIT();
            cp_wait<1>();
        } else cp_wait<0>();
        __syncthreads();
        unsigned a[4][4];
        load_afrag(a, QT(cur,0), arow, csel);
        mma_B(cq, a, QT(cur,1), lane);
        mma_B(ck, a, QT(cur,2), lane);
        mma_B(cv, a, QT(cur,3), lane);
        __syncthreads();
    }
    #undef QT

    const int o0g = g*GD + oo0;
    const int r0 = w*16 + (lane >> 2), q2 = 2*(lane & 3);
    const int b = m0 >> 10;
    const int s0 = (m0 & 1023) + r0;
    #pragma unroll
    for (int nb = 0; nb < 8; nb++) {
        int d = nb*8 + q2, bi = o0g + d;
        size_t ob0 = (((size_t)(b*NH + n))*SEQ + s0)*HD + d;
        size_t ob1 = ob0 + 8*HD;
        float w0 = rwb[bi], w1 = rwb[bi+1], r0b = rrb[bi], r1b = rrb[bi+1];
        *(unsigned*)&g_qw[ob0] = pk((cq[nb][0]+w0)*ATT_SCALE2, (cq[nb][1]+w1)*ATT_SCALE2);
        *(unsigned*)&g_qw[ob1] = pk((cq[nb][2]+w0)*ATT_SCALE2, (cq[nb][3]+w1)*ATT_SCALE2);
        *(unsigned*)&g_qr[ob0] = pk((cq[nb][0]+r0b)*ATT_SCALE2, (cq[nb][1]+r1b)*ATT_SCALE2);
        *(unsigned*)&g_qr[ob1] = pk((cq[nb][2]+r0b)*ATT_SCALE2, (cq[nb][3]+r1b)*ATT_SCALE2);
        float k0 = bk[bi], k1 = bk[bi+1];
        *(unsigned*)&g_k[ob0] = pk(ck[nb][0]+k0, ck[nb][1]+k1);
        *(unsigned*)&g_k[ob1] = pk(ck[nb][2]+k0, ck[nb][3]+k1);
        float v0 = bv[bi], v1 = bv[bi+1];
        *(unsigned*)&g_v[ob0] = pk(cv[nb][0]+v0, cv[nb][1]+v1);
        *(unsigned*)&g_v[ob1] = pk(cv[nb][2]+v0, cv[nb][3]+v1);
    }
}

// ---------------------------------------------------------------------------
// K1b: r_head = pe @ rk, 128x64 tiles.  grid (16, 12), dyn smem 48KB
// ---------------------------------------------------------------------------
#define RH_SMEM_BYTES 49152

__global__ void __launch_bounds__(128) rhead_kernel()
{
    extern __shared__ char rsm[];
    // stage s: A (128x64, 16KB) at s*24576, B (64x64, 8KB) at s*24576+16384
    #define RA(s) ((bf16*)(rsm + (s)*24576))
    #define RB(s) ((bf16*)(rsm + (s)*24576 + 16384))
    const int tid = threadIdx.x, lane = tid & 31, w = tid >> 5;
    const int t0 = blockIdx.x * 128;
    const int o0 = blockIdx.y * 64;
    const int vr = min(128, 2047 - t0);

    const bf16* srcA = g_peb + (size_t)t0*DM;
    const bf16* srcB = g_rkb + o0;

    float c0[8][4] = {}, c1[8][4] = {};

    async_bf16_tile(RA(0),          srcA,           DM, min(64, vr), tid);
    async_bf16_tile(RA(0) + 64*64,  srcA + 64*DM,   DM, vr - 64,     tid);
    async_bf16_tile(RB(0),          srcB,           DM, 64,          tid);
    CP_COMMIT();

    const int arow0 = w*32 + (lane & 15), arow1 = arow0 + 16, csel = lane >> 4;
    for (int i = 0; i < DM/64; i++) {
        int cur = i & 1, nxt = cur ^ 1;
        if (i + 1 < DM/64) {
            int kb = (i+1)*64;
            async_bf16_tile(RA(nxt),         srcA + kb,         DM, min(64, vr), tid);
            async_bf16_tile(RA(nxt) + 64*64, srcA + 64*DM + kb, DM, vr - 64,     tid);
            async_bf16_tile(RB(nxt),         srcB + (size_t)kb*DM, DM, 64,       tid);
            CP_COMMIT();
            cp_wait<1>();
        } else cp_wait<0>();
        __syncthreads();
        unsigned a0[4][4], a1[4][4];
        load_afrag(a0, RA(cur), arow0, csel);
        load_afrag(a1, RA(cur), arow1, csel);
        #pragma unroll
        for (int nbp = 0; nbp < 4; nbp++) {
            #pragma unroll
            for (int ks = 0; ks < 4; ks++) {
                int vrow = ks*16 + (lane & 15);
                int ch   = nbp*2 + (lane >> 4);
                unsigned b0, b1, b2, b3;
                ldm_x4t(b0, b1, b2, b3,
                        s2u((const char*)RB(cur) + vrow*128 + ((ch ^ (vrow&7)) << 4)));
                mma_bf16(c0[2*nbp],   a0[ks], b0, b1);
                mma_bf16(c0[2*nbp+1], a0[ks], b2, b3);
                mma_bf16(c1[2*nbp],   a1[ks], b0, b1);
                mma_bf16(c1[2*nbp+1], a1[ks], b2, b3);
            }
        }
        __syncthreads();
    }
    #undef RA
    #undef RB

    const int nHead = blockIdx.y;
    const int r0 = w*32 + (lane >> 2), q2 = 2*(lane & 3);
    #pragma unroll
    for (int nb = 0; nb < 8; nb++) {
        int d = nb*8 + q2;
        size_t base = ((size_t)nHead*2048 + t0 + r0)*HD + d;
        *(unsigned*)&g_rh[base]          = pk(c0[nb][0], c0[nb][1]);
        *(unsigned*)&g_rh[base + 8*HD]   = pk(c0[nb][2], c0[nb][3]);
        *(unsigned*)&g_rh[base + 16*HD]  = pk(c1[nb][0], c1[nb][1]);
        *(unsigned*)&g_rh[base + 24*HD]  = pk(c1[nb][2], c1[nb][3]);
    }
}

// ---------------------------------------------------------------------------
// K3: flash attention, cp.async pipeline, STATIC-max exp2 softmax.
// ---------------------------------------------------------------------------
#define RING_PITCH 132
#define ATT_SMEM_BYTES (40960 + 64*RING_PITCH*4)   // 74752

__device__ __forceinline__ void copy_tile64(bf16* dst, const bf16* src, int tid) {
    #pragma unroll
    for (int k = 0; k < 4; k++) {
        int c = tid + k*128, row = c >> 3, ch = c & 7;
        uint4 v = *(const uint4*)(src + (size_t)row*64 + ch*8);
        *(uint4*)((char*)dst + row*128 + ((ch ^ (row & 7)) << 4)) = v;
    }
}
__device__ __forceinline__ void load_rh_tile(bf16* dst, const bf16* src, int Tc, int tid) {
    #pragma unroll
    for (int k = 0; k < 4; k++) {
        int c = tid + k*128, row = c >> 3, ch = c & 7;
        int t = Tc + row;
        uint4 v = make_uint4(0u,0u,0u,0u);
        if (t >= 0 && t < 2048) v = *(const uint4*)(src + (size_t)t*64 + ch*8);
        *(uint4*)((char*)dst + row*128 + ((ch ^ (row & 7)) << 4)) = v;
    }
}
__device__ __forceinline__ void async_tile64(bf16* dst, const bf16* src, int tid) {
    #pragma unroll
    for (int k = 0; k < 4; k++) {
        int c = tid + k*128, row = c >> 3, ch = c & 7;
        cpa16(s2u((char*)dst + row*128 + ((ch ^ (row & 7)) << 4)),
              src + (size_t)row*64 + ch*8, 16);
    }
}
__device__ __forceinline__ void async_rh(bf16* dst, const bf16* src, int Tc, int tid) {
    #pragma unroll
    for (int k = 0; k < 4; k++) {
        int c = tid + k*128, row = c >> 3, ch = c & 7;
        int t = Tc + row;
        int sz = (t < 2048) ? 16 : 0;
        const bf16* p = src + (size_t)(t < 2048 ? t : 2047)*64 + ch*8;
        cpa16(s2u((char*)dst + row*128 + ((ch ^ (row & 7)) << 4)), p, sz);
    }
}

__device__ __forceinline__ void pos_mma_ring(
    const bf16* sRh, float* rp0, float* rp1, const unsigned (*qrA)[4],
    int Tc, int lane, int q2)
{
    #pragma unroll
    for (int nbp = 0; nbp < 4; nbp++) {
        float p0[4] = {0.f,0.f,0.f,0.f}, p1[4] = {0.f,0.f,0.f,0.f};
        int brow = nbp*16 + ((lane >> 4) << 3) + (lane & 7);
        #pragma unroll
        for (int ks = 0; ks < 4; ks++) {
            int ch = ks*2 + ((lane >> 3) & 1);
            unsigned b0, b1, b2, b3;
            ldm_x4(b0, b1, b2, b3,
                   s2u((const char*)sRh + brow*128 + ((ch ^ (brow & 7)) << 4)));
            mma_bf16(p0, qrA[ks], b0, b1);
            mma_bf16(p1, qrA[ks], b2, b3);
        }
        #pragma unroll
        for (int h = 0; h < 2; h++) {
            const float* pc = h ? p1 : p0;
            int s0 = (Tc + (nbp*2+h)*8 + q2) & 127;   // even, no wrap
            *(float2*)&rp0[s0] = make_float2(pc[0], pc[1]);
            *(float2*)&rp1[s0] = make_float2(pc[2], pc[3]);
        }
    }
}

__global__ void __launch_bounds__(128, 3) attn_kernel()
{
    extern __shared__ char smc[];
    bf16*  sK0  = (bf16*)(smc);
    bf16*  sK1  = (bf16*)(smc + 8192);
    bf16*  sRh0 = (bf16*)(smc + 16384);
    bf16*  sRh1 = (bf16*)(smc + 24576);
    bf16*  sV   = (bf16*)(smc + 32768);
    float* ring = (float*)(smc + 40960);

    const int tid = threadIdx.x, lane = tid & 31, w = tid >> 5;
    const int bn = blockIdx.y, n = bn % NH, b = bn / NH;
    const int i0 = blockIdx.x * 64;

    const bf16* qwB = g_qw + (size_t)bn * SEQ * HD;
    const bf16* qrB = g_qr + (size_t)bn * SEQ * HD;
    const bf16* kB  = g_k  + (size_t)bn * SEQ * HD;
    const bf16* vB  = g_v  + (size_t)bn * SEQ * HD;
    const bf16* rhB = g_rh + (size_t)n * 2048 * HD;

    copy_tile64(sK1, qwB + (size_t)i0*HD, tid);
    copy_tile64(sV,  qrB + (size_t)i0*HD, tid);
    load_rh_tile(sRh0, rhB, 960 - i0, tid);
    __syncthreads();

    async_tile64(sK0, kB, tid);
    async_rh(sRh1, rhB, 1024 - i0, tid);
    CP_COMMIT();

    unsigned qwA[4][4], qrA[4][4];
    {
        int arow = w*16 + (lane & 15);
        int csel = lane >> 4;
        load_afrag(qwA, sK1, arow, csel);
        load_afrag(qrA, sV,  arow, csel);
    }

    const int r0 = w*16 + (lane >> 2);
    const int q2 = 2*(lane & 3);
    float* rp0 = ring + r0*RING_PITCH;
    float* rp1 = ring + (r0+8)*RING_PITCH;
    const int tbase = 1024 + q2 - i0 - r0;

    float o[8][4] = {};
    float lrow0 = 0.f, lrow1 = 0.f;

    pos_mma_ring(sRh0, rp0, rp1, qrA, 960 - i0, lane, q2);

    for (int it = 0; it < 16; it++) {
        const int j0 = it * 64;
        bf16* Kc = (it & 1) ? sK1 : sK0;
        bf16* Kn = (it & 1) ? sK0 : sK1;
        bf16* Rc = (it & 1) ? sRh0 : sRh1;
        bf16* Rn = (it & 1) ? sRh1 : sRh0;

        __syncthreads();
        if (it < 15) {
            async_tile64(Kn, kB + (size_t)(j0+64)*HD, tid);
            async_rh(Rn, rhB, 1024 + (j0+64) - i0, tid);
            CP_COMMIT();
        }
        async_tile64(sV, vB + (size_t)j0*HD, tid);
        CP_COMMIT();
        if (it < 15) cp_wait<2>(); else cp_wait<1>();
        __syncthreads();

        float c[8][4] = {};
        #pragma unroll
        for (int nbp = 0; nbp < 4; nbp++) {
            int brow = nbp*16 + ((lane >> 4) << 3) + (lane & 7);
            #pragma unroll
            for (int ks = 0; ks < 4; ks++) {
                int ch = ks*2 + ((lane >> 3) & 1);
                unsigned b0, b1, b2, b3;
                ldm_x4(b0, b1, b2, b3,
                       s2u((char*)Kc + brow*128 + ((ch ^ (brow & 7)) << 4)));
                mma_bf16(c[2*nbp],   qwA[ks], b0, b1);
                mma_bf16(c[2*nbp+1], qwA[ks], b2, b3);
            }
        }
        pos_mma_ring(Rc, rp0, rp1, qrA, 1024 + j0 - i0, lane, q2);
        if (it < 15) cp_wait<1>(); else cp_wait<0>();
        __syncthreads();

        #pragma unroll
        for (int nb = 0; nb < 8; nb++) {
            int ta = tbase + j0 + nb*8;
            c[nb][0] += rp0[ta & 127];
            c[nb][1] += rp0[(ta + 1) & 127];
            c[nb][2] += rp1[(ta - 8) & 127];
            c[nb][3] += rp1[(ta - 7) & 127];
        }
        if (i0 == 0 && j0 == 960 && tid == 3) {
            float s = 0.f;
            #pragma unroll
            for (int d = 0; d < HD; d++)
                s += __bfloat162float(qrB[HD + d]) * __bfloat162float(rhB[d]);
            c[7][1] += s;
        }

        #pragma unroll
        for (int nb = 0; nb < 8; nb++) {
            c[nb][0] = ex2(c[nb][0] - SOFT_C); lrow0 += c[nb][0];
            c[nb][1] = ex2(c[nb][1] - SOFT_C); lrow0 += c[nb][1];
            c[nb][2] = ex2(c[nb][2] - SOFT_C); lrow1 += c[nb][2];
            c[nb][3] = ex2(c[nb][3] - SOFT_C); lrow1 += c[nb][3];
        }

        unsigned pa[4][4];
        #pragma unroll
        for (int ks = 0; ks < 4; ks++) {
            pa[ks][0] = pk(c[2*ks][0],   c[2*ks][1]);
            pa[ks][1] = pk(c[2*ks][2],   c[2*ks][3]);
            pa[ks][2] = pk(c[2*ks+1][0], c[2*ks+1][1]);
            pa[ks][3] = pk(c[2*ks+1][2], c[2*ks+1][3]);
        }
        #pragma unroll
        for (int nbp = 0; nbp < 4; nbp++) {
            #pragma unroll
            for (int ks = 0; ks < 4; ks++) {
                int vrow = ks*16 + (lane & 15);
                int ch   = nbp*2 + (lane >> 4);
                unsigned b0, b1, b2, b3;
                ldm_x4t(b0, b1, b2, b3,
                        s2u((char*)sV + vrow*128 + ((ch ^ (vrow & 7)) << 4)));
                mma_bf16(o[2*nbp],   pa[ks], b0, b1);
                mma_bf16(o[2*nbp+1], pa[ks], b2, b3);
            }
        }
    }

    lrow0 += __shfl_xor_sync(0xffffffffu, lrow0, 1);
    lrow0 += __shfl_xor_sync(0xffffffffu, lrow0, 2);
    lrow1 += __shfl_xor_sync(0xffffffffu, lrow1, 1);
    lrow1 += __shfl_xor_sync(0xffffffffu, lrow1, 2);
    float inv0 = 1.f / lrow0, inv1 = 1.f / lrow1;
    #pragma unroll
    for (int nb = 0; nb < 8; nb++) {
        int dd = nb*8 + q2;
        float a0 = o[nb][0]*inv0, a1 = o[nb][1]*inv0;
        float b0 = o[nb][2]*inv1, b1 = o[nb][3]*inv1;
        unsigned h0 = pk(a0, a1), h1 = pk(b0, b1);
        __nv_bfloat162 x0 = *(__nv_bfloat162*)&h0, x1 = *(__nv_bfloat162*)&h1;
        unsigned l0 = pk(a0 - __low2float(x0), a1 - __high2float(x0));
        unsigned l1 = pk(b0 - __low2float(x1), b1 - __high2float(x1));
        size_t ob0 = ((size_t)(b*SEQ + i0 + r0))*DM + n*HD + dd;
        size_t ob1 = ob0 + 8*DM;
        *(unsigned*)&g_avh[ob0] = h0;  *(unsigned*)&g_avl[ob0] = l0;
        *(unsigned*)&g_avh[ob1] = h1;  *(unsigned*)&g_avl[ob1] = l1;
    }
}

// ---------------------------------------------------------------------------
// K4: h = query + av @ Wo + bo  (split-bf16 MMA, cp.async pipelined).
// ---------------------------------------------------------------------------
#define PROJ_SMEM_BYTES 65536

__global__ void __launch_bounds__(128, 3) proj_kernel(
    const float* __restrict__ bo, const float* __restrict__ x)
{
    extern __shared__ char psm[];
    const int tid = threadIdx.x, lane = tid & 31, w = tid >> 5;
    const int m0 = blockIdx.x * 64;
    const int o0 = blockIdx.y * 64;
    float c[8][4] = {};

    const bf16* srcAh = g_avh + (size_t)m0*DM;
    const bf16* srcAl = g_avl + (size_t)m0*DM;
    const bf16* srcBh = g_woh + o0;
    const bf16* srcBl = g_wol + o0;

    #define PT(s, t) ((bf16*)(psm + (s)*32768 + (t)*8192))

    async_bf16_tile(PT(0,0), srcAh, DM, 64, tid);
    async_bf16_tile(PT(0,1), srcAl, DM, 64, tid);
    async_bf16_tile(PT(0,2), srcBh, DM, 64, tid);
    async_bf16_tile(PT(0,3), srcBl, DM, 64, tid);
    CP_COMMIT();

    const int NK = DM/64;
    for (int i = 0; i < NK; i++) {
        int cur = i & 1, nxt = cur ^ 1;
        if (i + 1 < NK) {
            int kb = (i+1)*64;
            async_bf16_tile(PT(nxt,0), srcAh + kb, DM, 64, tid);
            async_bf16_tile(PT(nxt,1), srcAl + kb, DM, 64, tid);
            async_bf16_tile(PT(nxt,2), srcBh + (size_t)kb*DM, DM, 64, tid);
            async_bf16_tile(PT(nxt,3), srcBl + (size_t)kb*DM, DM, 64, tid);
            CP_COMMIT();
            cp_wait<1>();
        } else cp_wait<0>();
        __syncthreads();

        bf16* sAh = PT(cur,0); bf16* sAl = PT(cur,1);
        bf16* sBh = PT(cur,2); bf16* sBl = PT(cur,3);

        unsigned ah[4][4], al[4][4];
        int arow = w*16 + (lane & 15), csel = lane >> 4;
        load_afrag(ah, sAh, arow, csel);
        load_afrag(al, sAl, arow, csel);
        #pragma unroll
        for (int nbp = 0; nbp < 4; nbp++) {
            #pragma unroll
            for (int ks = 0; ks < 4; ks++) {
                int vrow = ks*16 + (lane & 15);
                int ch   = nbp*2 + (lane >> 4);
                unsigned off = vrow*128 + ((ch ^ (vrow&7)) << 4);
                unsigned bh0, bh1, bh2, bh3, bl0, bl1, bl2, bl3;
                ldm_x4t(bh0, bh1, bh2, bh3, s2u((char*)sBh + off));
                ldm_x4t(bl0, bl1, bl2, bl3, s2u((char*)sBl + off));
                mma_bf16(c[2*nbp],   ah[ks], bh0, bh1);
                mma_bf16(c[2*nbp],   al[ks], bh0, bh1);
                mma_bf16(c[2*nbp],   ah[ks], bl0, bl1);
                mma_bf16(c[2*nbp+1], ah[ks], bh2, bh3);
                mma_bf16(c[2*nbp+1], al[ks], bh2, bh3);
                mma_bf16(c[2*nbp+1], ah[ks], bl2, bl3);
            }
        }
        __syncthreads();
    }
    #undef PT

    const int r0 = w*16 + (lane >> 2), q2 = 2*(lane & 3);
    #pragma unroll
    for (int nb = 0; nb < 8; nb++) {
        int col = o0 + nb*8 + q2;
        float b0 = bo[col], b1 = bo[col+1];
        size_t ob0 = (size_t)(m0 + r0)*DM + col;
        size_t ob1 = ob0 + 8*DM;
        float2 q0 = *(const float2*)&x[ob0];
        float2 q1 = *(const float2*)&x[ob1];
        *(float2*)&g_h[ob0] = make_float2(c[nb][0] + b0 + q0.x, c[nb][1] + b1 + q0.y);
        *(float2*)&g_h[ob1] = make_float2(c[nb][2] + b0 + q1.x, c[nb][3] + b1 + q1.y);
    }
}

// ---------------------------------------------------------------------------
// K5: LayerNorm.  grid (2048), 256 threads
// ---------------------------------------------------------------------------
__global__ void __launch_bounds__(256) ln_kernel(
    const float* __restrict__ gamma, const float* __restrict__ beta,
    float* __restrict__ out)
{
    __shared__ float red[16];
    const int row = blockIdx.x;
    const int tid = threadIdx.x;
    const float* h = g_h + (size_t)row * DM;
    float v0 = h[tid], v1 = h[tid+256], v2 = h[tid+512];
    float s = v0+v1+v2, ss = v0*v0+v1*v1+v2*v2;
    #pragma unroll
    for (int o = 16; o >= 1; o >>= 1) {
        s  += __shfl_xor_sync(0xffffffffu, s,  o);
        ss += __shfl_xor_sync(0xffffffffu, ss, o);
    }
    if ((tid & 31) == 0) { red[tid>>5] = s; red[8 + (tid>>5)] = ss; }
    __syncthreads();
    if (tid < 32) {
        float a = (tid < 8)  ? red[tid]     : 0.f;
        float b = (tid < 8)  ? red[8+tid]   : 0.f;
        #pragma unroll
        for (int o = 4; o >= 1; o >>= 1) {
            a += __shfl_xor_sync(0xffffffffu, a, o);
            b += __shfl_xor_sync(0xffffffffu, b, o);
        }
        if (tid == 0) { red[0] = a; red[1] = b; }
    }
    __syncthreads();
    float mu  = red[0] * (1.f/DM);
    float var = red[1] * (1.f/DM) - mu*mu;
    float inv = rsqrtf(var + 1e-9f);
    out[(size_t)row*DM + tid]     = (v0 - mu)*inv*gamma[tid]     + beta[tid];
    out[(size_t)row*DM + tid+256] = (v1 - mu)*inv*gamma[tid+256] + beta[tid+256];
    out[(size_t)row*DM + tid+512] = (v2 - mu)*inv*gamma[tid+512] + beta[tid+512];
}

// ---------------------------------------------------------------------------
extern "C" void kernel_launch(void* const* d_in, const int* in_sizes, int n_in,
                              void* d_out, int out_size)
{
    const float* query = (const float*)d_in[0];
    const float* pe    = (const float*)d_in[1];
    const float* Wq    = (const float*)d_in[2];
    const float* Wk    = (const float*)d_in[3];
    const float* bk    = (const float*)d_in[4];
    const float* Wv    = (const float*)d_in[5];
    const float* bv    = (const float*)d_in[6];
    const float* rk    = (const float*)d_in[7];
    const float* rwb   = (const float*)d_in[8];
    const float* rrb   = (const float*)d_in[9];
    const float* Wo    = (const float*)d_in[10];
    const float* bo    = (const float*)d_in[11];
    const float* gamma = (const float*)d_in[12];
    const float* beta  = (const float*)d_in[13];
    float* out = (float*)d_out;

    static bool attr_set = false;
    if (!attr_set) {
        cudaFuncSetAttribute(attn_kernel,
            cudaFuncAttributeMaxDynamicSharedMemorySize, ATT_SMEM_BYTES);
        cudaFuncSetAttribute(proj_kernel,
            cudaFuncAttributeMaxDynamicSharedMemorySize, PROJ_SMEM_BYTES);
        cudaFuncSetAttribute(qkvf_kernel,
            cudaFuncAttributeMaxDynamicSharedMemorySize, QKV_SMEM_BYTES);
        cudaFuncSetAttribute(rhead_kernel,
            cudaFuncAttributeMaxDynamicSharedMemorySize, RH_SMEM_BYTES);
        attr_set = true;
    }

    prep_kernel<<<dim3(256,7), 256>>>(query, pe, rk, Wq, Wk, Wv, Wo);
    qkvf_kernel<<<dim3(32,12), 128, QKV_SMEM_BYTES>>>(bk, bv, rwb, rrb);
    rhead_kernel<<<dim3(16,12), 128, RH_SMEM_BYTES>>>();
    attn_kernel<<<dim3(16,24), 128, ATT_SMEM_BYTES>>>();
    proj_kernel<<<dim3(32,12), 128, PROJ_SMEM_BYTES>>>(bo, query);
    ln_kernel<<<2048, 256>>>(gamma, beta, out);
}

// round 15
// speedup vs baseline: 1.0857x; 1.0857x over previous
#include <cuda_runtime.h>
#include <cuda_bf16.h>
#include <math.h>

#define BD   2
#define SEQ  1024
#define DM   768
#define NH   12
#define HD   64
#define GD   192
// ATT_SCALE * log2(e): scores come out pre-scaled for exp2-based softmax
#define ATT_SCALE2 (0.125f * 1.4426950408889634f)
#define SOFT_C 8.0f

typedef __nv_bfloat16 bf16;

// ------------------------------ scratch ------------------------------------
__device__ __align__(16) bf16 g_qw[BD*NH*SEQ*HD];
__device__ __align__(16) bf16 g_qr[BD*NH*SEQ*HD];
__device__ __align__(16) bf16 g_k [BD*NH*SEQ*HD];
__device__ __align__(16) bf16 g_v [BD*NH*SEQ*HD];
__device__ __align__(16) bf16 g_rh[NH*2048*HD];
__device__ __align__(16) bf16 g_avh[BD*SEQ*DM];
__device__ __align__(16) bf16 g_avl[BD*SEQ*DM];
__device__ __align__(16) bf16 g_woh[DM*DM];
__device__ __align__(16) bf16 g_xb [BD*SEQ*DM];
__device__ __align__(16) bf16 g_peb[2047*DM + 64];
__device__ __align__(16) bf16 g_rkb[DM*DM];
__device__ __align__(16) bf16 g_wb [3*4*GD*GD];
__device__ float g_h [BD*SEQ*DM];

// ------------------------------ helpers ------------------------------------
__device__ __forceinline__ unsigned pk(float lo, float hi) {
    __nv_bfloat162 h = __floats2bfloat162_rn(lo, hi);
    return *(unsigned*)&h;
}
__device__ __forceinline__ float ex2(float x) {
    float y;
    asm("ex2.approx.f32 %0, %1;" : "=f"(y) : "f"(x));
    return y;
}
__device__ __forceinline__ unsigned s2u(const void* p) {
    return (unsigned)__cvta_generic_to_shared(p);
}
__device__ __forceinline__ void ldm_x4(unsigned& r0, unsigned& r1, unsigned& r2, unsigned& r3, unsigned a) {
    asm volatile("ldmatrix.sync.aligned.m8n8.x4.shared.b16 {%0,%1,%2,%3},[%4];"
                 : "=r"(r0), "=r"(r1), "=r"(r2), "=r"(r3) : "r"(a));
}
__device__ __forceinline__ void ldm_x4t(unsigned& r0, unsigned& r1, unsigned& r2, unsigned& r3, unsigned a) {
    asm volatile("ldmatrix.sync.aligned.m8n8.x4.trans.shared.b16 {%0,%1,%2,%3},[%4];"
                 : "=r"(r0), "=r"(r1), "=r"(r2), "=r"(r3) : "r"(a));
}
__device__ __forceinline__ void mma_bf16(float* c, const unsigned* a, unsigned b0, unsigned b1) {
    asm volatile("mma.sync.aligned.m16n8k16.row.col.f32.bf16.bf16.f32 "
                 "{%0,%1,%2,%3},{%4,%5,%6,%7},{%8,%9},{%0,%1,%2,%3};"
                 : "+f"(c[0]), "+f"(c[1]), "+f"(c[2]), "+f"(c[3])
                 : "r"(a[0]), "r"(a[1]), "r"(a[2]), "r"(a[3]), "r"(b0), "r"(b1));
}
__device__ __forceinline__ void cpa16(unsigned dst, const void* src, int sz) {
    asm volatile("cp.async.cg.shared.global [%0], [%1], 16, %2;"
                 :: "r"(dst), "l"(src), "r"(sz));
}
#define CP_COMMIT() asm volatile("cp.async.commit_group;")
template<int N> __device__ __forceinline__ void cp_wait() {
    asm volatile("cp.async.wait_group %0;" :: "n"(N));
}

__device__ __forceinline__ void async_bf16_tile(bf16* dst, const bf16* src, int ld,
                                                int maxrow, int tid) {
    #pragma unroll
    for (int it = 0; it < 4; it++) {
        int c = tid + it*128, row = c >> 3, ch = c & 7;
        int sz = (row < maxrow) ? 16 : 0;
        int ar = (row < maxrow) ? row : (maxrow - 1);
        cpa16(s2u((char*)dst + row*128 + ((ch ^ (row&7)) << 4)),
              src + (size_t)ar*ld + ch*8, sz);
    }
}

__device__ __forceinline__ void load_afrag(unsigned (*a)[4], const bf16* sA,
                                           int arow, int csel) {
    #pragma unroll
    for (int ks = 0; ks < 4; ks++) {
        int ch = ks*2 + csel;
        ldm_x4(a[ks][0], a[ks][1], a[ks][2], a[ks][3],
               s2u((const char*)sA + arow*128 + ((ch ^ (arow&7)) << 4)));
    }
}

__device__ __forceinline__ void mma_tile(float (*c)[4], const bf16* sA, const bf16* sB,
                                         int lane, int w) {
    unsigned a[4][4];
    int arow = w*16 + (lane & 15), csel = lane >> 4;
    load_afrag(a, sA, arow, csel);
    #pragma unroll
    for (int nbp = 0; nbp < 4; nbp++) {
        #pragma unroll
        for (int ks = 0; ks < 4; ks++) {
            int vrow = ks*16 + (lane & 15);
            int ch   = nbp*2 + (lane >> 4);
            unsigned b0, b1, b2, b3;
            ldm_x4t(b0, b1, b2, b3,
                    s2u((const char*)sB + vrow*128 + ((ch ^ (vrow&7)) << 4)));
            mma_bf16(c[2*nbp],   a[ks], b0, b1);
            mma_bf16(c[2*nbp+1], a[ks], b2, b3);
        }
    }
}

// ---------------------------------------------------------------------------
// K0: fp32->bf16 conversions + Wo hi conversion. grid (256, 7)
// ---------------------------------------------------------------------------
__global__ void __launch_bounds__(256) prep_kernel(
    const float* __restrict__ x,  const float* __restrict__ pe,
    const float* __restrict__ rk, const float* __restrict__ Wq,
    const float* __restrict__ Wk, const float* __restrict__ Wv,
    const float* __restrict__ Wo)
{
    const int seg = blockIdx.y;
    const float* src; bf16* dst; int n4;
    switch (seg) {
        case 0: src = x;  dst = g_xb;  n4 = BD*SEQ*DM/4;   break;
        case 1: src = pe; dst = g_peb; n4 = 2047*DM/4;     break;
        case 2: src = rk; dst = g_rkb; n4 = DM*DM/4;       break;
        case 3: src = Wq; dst = g_wb;            n4 = GD*GD; break;
        case 4: src = Wk; dst = g_wb + 4*GD*GD;  n4 = GD*GD; break;
        case 5: src = Wv; dst = g_wb + 8*GD*GD;  n4 = GD*GD; break;
        default: src = Wo; dst = g_woh; n4 = DM*DM/4; break;
    }
    for (int i = blockIdx.x*256 + threadIdx.x; i < n4; i += gridDim.x*256) {
        float4 v = *(const float4*)&src[i*4];
        *(uint2*)&dst[i*4] = make_uint2(pk(v.x, v.y), pk(v.z, v.w));
    }
}

// ---------------------------------------------------------------------------
// K1: grouped QKV + r_head GEMMs, cp.async pipelined. grid (32, 12, 4)
// ---------------------------------------------------------------------------
__global__ void __launch_bounds__(128) qkvr_kernel(
    const float* __restrict__ bk, const float* __restrict__ bv,
    const float* __restrict__ rwb, const float* __restrict__ rrb)
{
    __shared__ bf16 sA[2][64*64], sB[2][64*64];
    const int tid = threadIdx.x, lane = tid & 31, w = tid >> 5;
    const int z = blockIdx.z;
    float c[8][4] = {};
    const int r0 = w*16 + (lane >> 2), q2 = 2*(lane & 3);

    const bf16 *srcA, *srcB;
    int ldA, ldB, maxA, nk;
    if (z == 3) {
        const int t0 = blockIdx.x * 64, o0 = blockIdx.y * 64;
        srcA = g_peb + (size_t)t0*DM;  ldA = DM;  maxA = min(64, 2047 - t0);
        srcB = g_rkb + o0;             ldB = DM;
        nk = DM/64;
    } else {
        const int m0 = blockIdx.x * 64;
        const int g  = blockIdx.y / 3, oo0 = (blockIdx.y % 3) * 64;
        srcA = g_xb + (size_t)m0*DM + g*GD;                 ldA = DM; maxA = 64;
        srcB = g_wb + (size_t)z*4*GD*GD + g*GD*GD + oo0;    ldB = GD;
        nk = GD/64;
    }

    async_bf16_tile(sA[0], srcA, ldA, maxA, tid);
    async_bf16_tile(sB[0], srcB, ldB, 64, tid);
    CP_COMMIT();

    for (int i = 0; i < nk; i++) {
        int cur = i & 1, nxt = cur ^ 1;
        if (i + 1 < nk) {
            async_bf16_tile(sA[nxt], srcA + (i+1)*64, ldA, maxA, tid);
            async_bf16_tile(sB[nxt], srcB + (size_t)(i+1)*64*ldB, ldB, 64, tid);
            CP_COMMIT();
            cp_wait<1>();
        } else cp_wait<0>();
        __syncthreads();
        mma_tile(c, sA[cur], sB[cur], lane, w);
        __syncthreads();
    }

    if (z == 3) {
        const int t0 = blockIdx.x * 64, n = blockIdx.y;
        #pragma unroll
        for (int nb = 0; nb < 8; nb++) {
            int d = nb*8 + q2;
            size_t ob0 = ((size_t)n*2048 + t0 + r0)*HD + d;
            *(unsigned*)&g_rh[ob0]        = pk(c[nb][0], c[nb][1]);
            *(unsigned*)&g_rh[ob0 + 8*HD] = pk(c[nb][2], c[nb][3]);
        }
        return;
    }

    const int m0 = blockIdx.x * 64;
    const int g  = blockIdx.y / 3, oo0 = (blockIdx.y % 3) * 64;
    const int n = blockIdx.y;
    const int o0g = g*GD + oo0;
    const int b = m0 >> 10;
    const int s0 = (m0 & 1023) + r0;
    #pragma unroll
    for (int nb = 0; nb < 8; nb++) {
        int d = nb*8 + q2, bi = o0g + d;
        size_t ob0 = (((size_t)(b*NH + n))*SEQ + s0)*HD + d;
        size_t ob1 = ob0 + 8*HD;
        if (z == 0) {
            float w0 = rwb[bi], w1 = rwb[bi+1], r0b = rrb[bi], r1b = rrb[bi+1];
            *(unsigned*)&g_qw[ob0] = pk((c[nb][0]+w0)*ATT_SCALE2, (c[nb][1]+w1)*ATT_SCALE2);
            *(unsigned*)&g_qw[ob1] = pk((c[nb][2]+w0)*ATT_SCALE2, (c[nb][3]+w1)*ATT_SCALE2);
            *(unsigned*)&g_qr[ob0] = pk((c[nb][0]+r0b)*ATT_SCALE2, (c[nb][1]+r1b)*ATT_SCALE2);
            *(unsigned*)&g_qr[ob1] = pk((c[nb][2]+r0b)*ATT_SCALE2, (c[nb][3]+r1b)*ATT_SCALE2);
        } else if (z == 1) {
            float b0 = bk[bi], b1 = bk[bi+1];
            *(unsigned*)&g_k[ob0] = pk(c[nb][0]+b0, c[nb][1]+b1);
            *(unsigned*)&g_k[ob1] = pk(c[nb][2]+b0, c[nb][3]+b1);
        } else {
            float b0 = bv[bi], b1 = bv[bi+1];
            *(unsigned*)&g_v[ob0] = pk(c[nb][0]+b0, c[nb][1]+b1);
            *(unsigned*)&g_v[ob1] = pk(c[nb][2]+b0, c[nb][3]+b1);
        }
    }
}

// ---------------------------------------------------------------------------
// K3: flash attention, cp.async pipeline, STATIC-max exp2 softmax.
// ---------------------------------------------------------------------------
#define RING_PITCH 132
#define ATT_SMEM_BYTES (40960 + 64*RING_PITCH*4)   // 74752

__device__ __forceinline__ void copy_tile64(bf16* dst, const bf16* src, int tid) {
    #pragma unroll
    for (int k = 0; k < 4; k++) {
        int c = tid + k*128, row = c >> 3, ch = c & 7;
        uint4 v = *(const uint4*)(src + (size_t)row*64 + ch*8);
        *(uint4*)((char*)dst + row*128 + ((ch ^ (row & 7)) << 4)) = v;
    }
}
__device__ __forceinline__ void load_rh_tile(bf16* dst, const bf16* src, int Tc, int tid) {
    #pragma unroll
    for (int k = 0; k < 4; k++) {
        int c = tid + k*128, row = c >> 3, ch = c & 7;
        int t = Tc + row;
        uint4 v = make_uint4(0u,0u,0u,0u);
        if (t >= 0 && t < 2048) v = *(const uint4*)(src + (size_t)t*64 + ch*8);
        *(uint4*)((char*)dst + row*128 + ((ch ^ (row & 7)) << 4)) = v;
    }
}
__device__ __forceinline__ void async_tile64(bf16* dst, const bf16* src, int tid) {
    #pragma unroll
    for (int k = 0; k < 4; k++) {
        int c = tid + k*128, row = c >> 3, ch = c & 7;
        cpa16(s2u((char*)dst + row*128 + ((ch ^ (row & 7)) << 4)),
              src + (size_t)row*64 + ch*8, 16);
    }
}
__device__ __forceinline__ void async_rh(bf16* dst, const bf16* src, int Tc, int tid) {
    #pragma unroll
    for (int k = 0; k < 4; k++) {
        int c = tid + k*128, row = c >> 3, ch = c & 7;
        int t = Tc + row;
        int sz = (t < 2048) ? 16 : 0;
        const bf16* p = src + (size_t)(t < 2048 ? t : 2047)*64 + ch*8;
        cpa16(s2u((char*)dst + row*128 + ((ch ^ (row & 7)) << 4)), p, sz);
    }
}

__device__ __forceinline__ void pos_mma_ring(
    const bf16* sRh, float* rp0, float* rp1, const unsigned (*qrA)[4],
    int Tc, int lane, int q2)
{
    #pragma unroll
    for (int nbp = 0; nbp < 4; nbp++) {
        float p0[4] = {0.f,0.f,0.f,0.f}, p1[4] = {0.f,0.f,0.f,0.f};
        int brow = nbp*16 + ((lane >> 4) << 3) + (lane & 7);
        #pragma unroll
        for (int ks = 0; ks < 4; ks++) {
            int ch = ks*2 + ((lane >> 3) & 1);
            unsigned b0, b1, b2, b3;
            ldm_x4(b0, b1, b2, b3,
                   s2u((const char*)sRh + brow*128 + ((ch ^ (brow & 7)) << 4)));
            mma_bf16(p0, qrA[ks], b0, b1);
            mma_bf16(p1, qrA[ks], b2, b3);
        }
        #pragma unroll
        for (int h = 0; h < 2; h++) {
            const float* pc = h ? p1 : p0;
            int s0 = (Tc + (nbp*2+h)*8 + q2) & 127;   // even, no wrap
            *(float2*)&rp0[s0] = make_float2(pc[0], pc[1]);
            *(float2*)&rp1[s0] = make_float2(pc[2], pc[3]);
        }
    }
}

__global__ void __launch_bounds__(128, 3) attn_kernel()
{
    extern __shared__ char smc[];
    bf16*  sK0  = (bf16*)(smc);
    bf16*  sK1  = (bf16*)(smc + 8192);
    bf16*  sRh0 = (bf16*)(smc + 16384);
    bf16*  sRh1 = (bf16*)(smc + 24576);
    bf16*  sV   = (bf16*)(smc + 32768);
    float* ring = (float*)(smc + 40960);

    const int tid = threadIdx.x, lane = tid & 31, w = tid >> 5;
    const int bn = blockIdx.y, n = bn % NH, b = bn / NH;
    const int i0 = blockIdx.x * 64;

    const bf16* qwB = g_qw + (size_t)bn * SEQ * HD;
    const bf16* qrB = g_qr + (size_t)bn * SEQ * HD;
    const bf16* kB  = g_k  + (size_t)bn * SEQ * HD;
    const bf16* vB  = g_v  + (size_t)bn * SEQ * HD;
    const bf16* rhB = g_rh + (size_t)n * 2048 * HD;

    copy_tile64(sK1, qwB + (size_t)i0*HD, tid);
    copy_tile64(sV,  qrB + (size_t)i0*HD, tid);
    load_rh_tile(sRh0, rhB, 960 - i0, tid);
    __syncthreads();

    async_tile64(sK0, kB, tid);
    async_rh(sRh1, rhB, 1024 - i0, tid);
    CP_COMMIT();

    unsigned qwA[4][4], qrA[4][4];
    {
        int arow = w*16 + (lane & 15);
        int csel = lane >> 4;
        load_afrag(qwA, sK1, arow, csel);
        load_afrag(qrA, sV,  arow, csel);
    }

    const int r0 = w*16 + (lane >> 2);
    const int q2 = 2*(lane & 3);
    float* rp0 = ring + r0*RING_PITCH;
    float* rp1 = ring + (r0+8)*RING_PITCH;
    const int tbase = 1024 + q2 - i0 - r0;

    float o[8][4] = {};
    float lrow0 = 0.f, lrow1 = 0.f;

    pos_mma_ring(sRh0, rp0, rp1, qrA, 960 - i0, lane, q2);

    for (int it = 0; it < 16; it++) {
        const int j0 = it * 64;
        bf16* Kc = (it & 1) ? sK1 : sK0;
        bf16* Kn = (it & 1) ? sK0 : sK1;
        bf16* Rc = (it & 1) ? sRh0 : sRh1;
        bf16* Rn = (it & 1) ? sRh1 : sRh0;

        __syncthreads();
        if (it < 15) {
            async_tile64(Kn, kB + (size_t)(j0+64)*HD, tid);
            async_rh(Rn, rhB, 1024 + (j0+64) - i0, tid);
            CP_COMMIT();
        }
        async_tile64(sV, vB + (size_t)j0*HD, tid);
        CP_COMMIT();
        if (it < 15) cp_wait<2>(); else cp_wait<1>();
        __syncthreads();

        float c[8][4] = {};
        #pragma unroll
        for (int nbp = 0; nbp < 4; nbp++) {
            int brow = nbp*16 + ((lane >> 4) << 3) + (lane & 7);
            #pragma unroll
            for (int ks = 0; ks < 4; ks++) {
                int ch = ks*2 + ((lane >> 3) & 1);
                unsigned b0, b1, b2, b3;
                ldm_x4(b0, b1, b2, b3,
                       s2u((char*)Kc + brow*128 + ((ch ^ (brow & 7)) << 4)));
                mma_bf16(c[2*nbp],   qwA[ks], b0, b1);
                mma_bf16(c[2*nbp+1], qwA[ks], b2, b3);
            }
        }
        pos_mma_ring(Rc, rp0, rp1, qrA, 1024 + j0 - i0, lane, q2);
        if (it < 15) cp_wait<1>(); else cp_wait<0>();
        __syncthreads();

        #pragma unroll
        for (int nb = 0; nb < 8; nb++) {
            int ta = tbase + j0 + nb*8;
            c[nb][0] += rp0[ta & 127];
            c[nb][1] += rp0[(ta + 1) & 127];
            c[nb][2] += rp1[(ta - 8) & 127];
            c[nb][3] += rp1[(ta - 7) & 127];
        }
        if (i0 == 0 && j0 == 960 && tid == 3) {
            float s = 0.f;
            #pragma unroll
            for (int d = 0; d < HD; d++)
                s += __bfloat162float(qrB[HD + d]) * __bfloat162float(rhB[d]);
            c[7][1] += s;
        }

        #pragma unroll
        for (int nb = 0; nb < 8; nb++) {
            c[nb][0] = ex2(c[nb][0] - SOFT_C); lrow0 += c[nb][0];
            c[nb][1] = ex2(c[nb][1] - SOFT_C); lrow0 += c[nb][1];
            c[nb][2] = ex2(c[nb][2] - SOFT_C); lrow1 += c[nb][2];
            c[nb][3] = ex2(c[nb][3] - SOFT_C); lrow1 += c[nb][3];
        }

        unsigned pa[4][4];
        #pragma unroll
        for (int ks = 0; ks < 4; ks++) {
            pa[ks][0] = pk(c[2*ks][0],   c[2*ks][1]);
            pa[ks][1] = pk(c[2*ks][2],   c[2*ks][3]);
            pa[ks][2] = pk(c[2*ks+1][0], c[2*ks+1][1]);
            pa[ks][3] = pk(c[2*ks+1][2], c[2*ks+1][3]);
        }
        #pragma unroll
        for (int nbp = 0; nbp < 4; nbp++) {
            #pragma unroll
            for (int ks = 0; ks < 4; ks++) {
                int vrow = ks*16 + (lane & 15);
                int ch   = nbp*2 + (lane >> 4);
                unsigned b0, b1, b2, b3;
                ldm_x4t(b0, b1, b2, b3,
                        s2u((char*)sV + vrow*128 + ((ch ^ (vrow & 7)) << 4)));
                mma_bf16(o[2*nbp],   pa[ks], b0, b1);
                mma_bf16(o[2*nbp+1], pa[ks], b2, b3);
            }
        }
    }

    lrow0 += __shfl_xor_sync(0xffffffffu, lrow0, 1);
    lrow0 += __shfl_xor_sync(0xffffffffu, lrow0, 2);
    lrow1 += __shfl_xor_sync(0xffffffffu, lrow1, 1);
    lrow1 += __shfl_xor_sync(0xffffffffu, lrow1, 2);
    float inv0 = 1.f / lrow0, inv1 = 1.f / lrow1;
    #pragma unroll
    for (int nb = 0; nb < 8; nb++) {
        int dd = nb*8 + q2;
        float a0 = o[nb][0]*inv0, a1 = o[nb][1]*inv0;
        float b0 = o[nb][2]*inv1, b1 = o[nb][3]*inv1;
        unsigned h0 = pk(a0, a1), h1 = pk(b0, b1);
        __nv_bfloat162 x0 = *(__nv_bfloat162*)&h0, x1 = *(__nv_bfloat162*)&h1;
        unsigned l0 = pk(a0 - __low2float(x0), a1 - __high2float(x0));
        unsigned l1 = pk(b0 - __low2float(x1), b1 - __high2float(x1));
        size_t ob0 = ((size_t)(b*SEQ + i0 + r0))*DM + n*HD + dd;
        size_t ob1 = ob0 + 8*DM;
        *(unsigned*)&g_avh[ob0] = h0;  *(unsigned*)&g_avl[ob0] = l0;
        *(unsigned*)&g_avh[ob1] = h1;  *(unsigned*)&g_avl[ob1] = l1;
    }
}

// ---------------------------------------------------------------------------
// K4: h = query + av @ Wo + bo  (2-chain split-bf16 MMA: Ah*Bh + Al*Bh).
// smem: 2 stages x 3 tiles x 8KB = 48KB dynamic.  grid (32, 12)
// ---------------------------------------------------------------------------
#define PROJ_SMEM_BYTES 49152

__global__ void __launch_bounds__(128, 3) proj_kernel(
    const float* __restrict__ bo, const float* __restrict__ x)
{
    extern __shared__ char psm[];
    const int tid = threadIdx.x, lane = tid & 31, w = tid >> 5;
    const int m0 = blockIdx.x * 64;
    const int o0 = blockIdx.y * 64;
    float c[8][4] = {};

    const bf16* srcAh = g_avh + (size_t)m0*DM;
    const bf16* srcAl = g_avl + (size_t)m0*DM;
    const bf16* srcBh = g_woh + o0;

    #define PT(s, t) ((bf16*)(psm + (s)*24576 + (t)*8192))

    async_bf16_tile(PT(0,0), srcAh, DM, 64, tid);
    async_bf16_tile(PT(0,1), srcAl, DM, 64, tid);
    async_bf16_tile(PT(0,2), srcBh, DM, 64, tid);
    CP_COMMIT();

    const int NK = DM/64;
    for (int i = 0; i < NK; i++) {
        int cur = i & 1, nxt = cur ^ 1;
        if (i + 1 < NK) {
            int kb = (i+1)*64;
            async_bf16_tile(PT(nxt,0), srcAh + kb, DM, 64, tid);
            async_bf16_tile(PT(nxt,1), srcAl + kb, DM, 64, tid);
            async_bf16_tile(PT(nxt,2), srcBh + (size_t)kb*DM, DM, 64, tid);
            CP_COMMIT();
            cp_wait<1>();
        } else cp_wait<0>();
        __syncthreads();

        bf16* sAh = PT(cur,0); bf16* sAl = PT(cur,1); bf16* sBh = PT(cur,2);

        unsigned ah[4][4], al[4][4];
        int arow = w*16 + (lane & 15), csel = lane >> 4;
        load_afrag(ah, sAh, arow, csel);
        load_afrag(al, sAl, arow, csel);
        #pragma unroll
        for (int nbp = 0; nbp < 4; nbp++) {
            #pragma unroll
            for (int ks = 0; ks < 4; ks++) {
                int vrow = ks*16 + (lane & 15);
                int ch   = nbp*2 + (lane >> 4);
                unsigned off = vrow*128 + ((ch ^ (vrow&7)) << 4);
                unsigned bh0, bh1, bh2, bh3;
                ldm_x4t(bh0, bh1, bh2, bh3, s2u((char*)sBh + off));
                mma_bf16(c[2*nbp],   ah[ks], bh0, bh1);
                mma_bf16(c[2*nbp],   al[ks], bh0, bh1);
                mma_bf16(c[2*nbp+1], ah[ks], bh2, bh3);
                mma_bf16(c[2*nbp+1], al[ks], bh2, bh3);
            }
        }
        __syncthreads();
    }
    #undef PT

    const int r0 = w*16 + (lane >> 2), q2 = 2*(lane & 3);
    #pragma unroll
    for (int nb = 0; nb < 8; nb++) {
        int col = o0 + nb*8 + q2;
        float b0 = bo[col], b1 = bo[col+1];
        size_t ob0 = (size_t)(m0 + r0)*DM + col;
        size_t ob1 = ob0 + 8*DM;
        float2 q0 = *(const float2*)&x[ob0];
        float2 q1 = *(const float2*)&x[ob1];
        *(float2*)&g_h[ob0] = make_float2(c[nb][0] + b0 + q0.x, c[nb][1] + b1 + q0.y);
        *(float2*)&g_h[ob1] = make_float2(c[nb][2] + b0 + q1.x, c[nb][3] + b1 + q1.y);
    }
}

// ---------------------------------------------------------------------------
// K5: LayerNorm.  grid (2048), 256 threads
// ---------------------------------------------------------------------------
__global__ void __launch_bounds__(256) ln_kernel(
    const float* __restrict__ gamma, const float* __restrict__ beta,
    float* __restrict__ out)
{
    __shared__ float red[16];
    const int row = blockIdx.x;
    const int tid = threadIdx.x;
    const float* h = g_h + (size_t)row * DM;
    float v0 = h[tid], v1 = h[tid+256], v2 = h[tid+512];
    float s = v0+v1+v2, ss = v0*v0+v1*v1+v2*v2;
    #pragma unroll
    for (int o = 16; o >= 1; o >>= 1) {
        s  += __shfl_xor_sync(0xffffffffu, s,  o);
        ss += __shfl_xor_sync(0xffffffffu, ss, o);
    }
    if ((tid & 31) == 0) { red[tid>>5] = s; red[8 + (tid>>5)] = ss; }
    __syncthreads();
    if (tid < 32) {
        float a = (tid < 8)  ? red[tid]     : 0.f;
        float b = (tid < 8)  ? red[8+tid]   : 0.f;
        #pragma unroll
        for (int o = 4; o >= 1; o >>= 1) {
            a += __shfl_xor_sync(0xffffffffu, a, o);
            b += __shfl_xor_sync(0xffffffffu, b, o);
        }
        if (tid == 0) { red[0] = a; red[1] = b; }
    }
    __syncthreads();
    float mu  = red[0] * (1.f/DM);
    float var = red[1] * (1.f/DM) - mu*mu;
    float inv = rsqrtf(var + 1e-9f);
    out[(size_t)row*DM + tid]     = (v0 - mu)*inv*gamma[tid]     + beta[tid];
    out[(size_t)row*DM + tid+256] = (v1 - mu)*inv*gamma[tid+256] + beta[tid+256];
    out[(size_t)row*DM + tid+512] = (v2 - mu)*inv*gamma[tid+512] + beta[tid+512];
}

// ---------------------------------------------------------------------------
extern "C" void kernel_launch(void* const* d_in, const int* in_sizes, int n_in,
                              void* d_out, int out_size)
{
    const float* query = (const float*)d_in[0];
    const float* pe    = (const float*)d_in[1];
    const float* Wq    = (const float*)d_in[2];
    const float* Wk    = (const float*)d_in[3];
    const float* bk    = (const float*)d_in[4];
    const float* Wv    = (const float*)d_in[5];
    const float* bv    = (const float*)d_in[6];
    const float* rk    = (const float*)d_in[7];
    const float* rwb   = (const float*)d_in[8];
    const float* rrb   = (const float*)d_in[9];
    const float* Wo    = (const float*)d_in[10];
    const float* bo    = (const float*)d_in[11];
    const float* gamma = (const float*)d_in[12];
    const float* beta  = (const float*)d_in[13];
    float* out = (float*)d_out;

    static bool attr_set = false;
    if (!attr_set) {
        cudaFuncSetAttribute(attn_kernel,
            cudaFuncAttributeMaxDynamicSharedMemorySize, ATT_SMEM_BYTES);
        cudaFuncSetAttribute(proj_kernel,
            cudaFuncAttributeMaxDynamicSharedMemorySize, PROJ_SMEM_BYTES);
        attr_set = true;
    }

    prep_kernel<<<dim3(256,7), 256>>>(query, pe, rk, Wq, Wk, Wv, Wo);
    qkvr_kernel<<<dim3(32,12,4), 128>>>(bk, bv, rwb, rrb);
    attn_kernel<<<dim3(16,24), 128, ATT_SMEM_BYTES>>>();
    proj_kernel<<<dim3(32,12), 128, PROJ_SMEM_BYTES>>>(bo, query);
    ln_kernel<<<2048, 256>>>(gamma, beta, out);
}